// round 4
// baseline (speedup 1.0000x reference)
#include <cuda_runtime.h>

// SNN XORNet, T=20 LIF. Now latency/occupancy-bound (ncu R3: issue=61%, occ=38%,
// no pipe saturated, regs=68). This round: loop rotation so spikes s1 are body-local
// instead of live across the t-loop back-edge (they were 16 of the 68 registers).
// Carried state per t: pre-spike membranes m1,m2 and prev spk2 only.
// Identical IEEE op sequence per value as rounds 1-3 -> bit-identical output.

#define T_STEPS 20
#define BETA    0.9f
#define THR     1.0f

typedef unsigned long long u64;

__device__ __forceinline__ u64 pack2(float lo, float hi) {
    u64 r; asm("mov.b64 %0, {%1, %2};" : "=l"(r) : "f"(lo), "f"(hi)); return r;
}
__device__ __forceinline__ void unpack2(u64 v, float& lo, float& hi) {
    asm("mov.b64 {%0, %1}, %2;" : "=f"(lo), "=f"(hi) : "l"(v));
}
__device__ __forceinline__ u64 fma2(u64 a, u64 b, u64 c) {
    u64 r; asm("fma.rn.f32x2 %0, %1, %2, %3;" : "=l"(r) : "l"(a), "l"(b), "l"(c)); return r;
}
__device__ __forceinline__ float fset_gt(float a, float b) {
    float r; asm("set.gt.f32.f32 %0, %1, %2;" : "=f"(r) : "f"(a), "f"(b)); return r;
}
// packed spike: {lo>1?1:0, hi>1?1:0}
__device__ __forceinline__ u64 spike2(u64 m) {
    float lo, hi; unpack2(m, lo, hi);
    return pack2(fset_gt(lo, THR), fset_gt(hi, THR));
}

__global__ __launch_bounds__(128)
void snn_kernel(const float* __restrict__ x,
                const float* __restrict__ w1,   // [4,2]
                const float* __restrict__ w2,   // [1,4]
                float* __restrict__ out,        // [T, B]
                int B)
{
    const int tid = blockIdx.x * blockDim.x + threadIdx.x;
    const int i0  = tid * 4;                    // 4 batch elements = 2 f32x2 pairs
    if (i0 >= B) return;

    float w1v[8];
#pragma unroll
    for (int k = 0; k < 8; k++) w1v[k] = __ldg(w1 + k);
    u64 w2p[4];
#pragma unroll
    for (int k = 0; k < 4; k++) { float w = __ldg(w2 + k); w2p[k] = pack2(w, w); }

    const u64 BETA2 = pack2(BETA, BETA);
    const u64 NEG1  = pack2(-1.f, -1.f);

    const float4* xv = reinterpret_cast<const float4*>(x + 2 * (size_t)i0);
    float4 xa = xv[0];
    float4 xb = xv[1];
    float xe[4][2] = {{xa.x, xa.y}, {xa.z, xa.w}, {xb.x, xb.y}, {xb.z, xb.w}};

    // cur (timestep-invariant), packed per pair — same scalar math as R1.
    u64 cur2[2][4];
#pragma unroll
    for (int p = 0; p < 2; p++)
#pragma unroll
        for (int h = 0; h < 4; h++) {
            float c0 = fmaf(xe[2*p  ][1], w1v[2*h+1], xe[2*p  ][0] * w1v[2*h]);
            float c1 = fmaf(xe[2*p+1][1], w1v[2*h+1], xe[2*p+1][0] * w1v[2*h]);
            cur2[p][h] = pack2(c0, c1);
        }

    // Rotated state: pre-spike membranes at step t. t=0: m1 = beta*0 + cur - 0 = cur (exact).
    u64 m1[2][4], m2[2], s2[2];
#pragma unroll
    for (int p = 0; p < 2; p++) {
#pragma unroll
        for (int h = 0; h < 4; h++) m1[p][h] = cur2[p][h];
        m2[p] = 0ull;                   // filled in first iteration from acc
        s2[p] = 0ull;                   // spk2(-1) = 0
    }

    float* outp = out + i0;
    const size_t stride = (size_t)B;

#pragma unroll 1
    for (int t = 0; t < T_STEPS; t++) {
        float4 o;
        float* op = &o.x;
#pragma unroll
        for (int p = 0; p < 2; p++) {
            u64 acc = 0ull;
            u64 s1[4];                  // body-local: not live across back-edge
#pragma unroll
            for (int h = 0; h < 4; h++) {
                s1[h] = spike2(m1[p][h]);               // spk1_t = (m1_t > 1)
                acc = fma2(s1[h], w2p[h], acc);         // out_t += spk1*w2
            }
            // layer2: m2_t = beta*m2_{t-1} + out_t - spk2_{t-1}
            m2[p] = fma2(BETA2, m2[p], acc);
            m2[p] = fma2(s2[p], NEG1, m2[p]);
            s2[p] = spike2(m2[p]);                      // spk2_t (carried + stored)
            float lo, hi; unpack2(s2[p], lo, hi);
            op[2*p]   = lo;
            op[2*p+1] = hi;
            // advance layer1: m1_{t+1} = beta*m1_t + cur - spk1_t
#pragma unroll
            for (int h = 0; h < 4; h++) {
                m1[p][h] = fma2(BETA2, m1[p][h], cur2[p][h]);
                m1[p][h] = fma2(s1[h], NEG1, m1[p][h]);
            }
        }
        *reinterpret_cast<float4*>(outp + (size_t)t * stride) = o;  // coalesced 128b
    }
}

extern "C" void kernel_launch(void* const* d_in, const int* in_sizes, int n_in,
                              void* d_out, int out_size)
{
    const float* x  = (const float*)d_in[0];   // [B,2]
    const float* w1 = (const float*)d_in[1];   // [4,2]
    const float* w2 = (const float*)d_in[2];   // [1,4]
    float* out = (float*)d_out;                // [T,B,1]

    const int B = in_sizes[0] / 2;             // 1,048,576
    const int elems_per_thread = 4;
    const int nthreads = (B + elems_per_thread - 1) / elems_per_thread;
    const int block = 128;
    const int grid = (nthreads + block - 1) / block;

    snn_kernel<<<grid, block>>>(x, w1, w2, out, B);
}